// round 2
// baseline (speedup 1.0000x reference)
#include <cuda_runtime.h>
#include <math.h>

#define B 64
#define T 1024
#define E 512
#define R 1024
#define A 128
#define F 32
#define KS 31
#define PADC 15

#define BT 64
#define KC 32

// scratch (allocation-free rule: __device__ globals)
__device__ float g_q[B * A];                       // 32 KB
__device__ float g_loc[(size_t)B * T * A];         // 32 MB
__device__ float g_e[B * T];                       // 256 KB
__device__ float g_ctxpart[B * 8 * E];             // 1 MB
__device__ int   g_maskmode;                       // 0=u8, 1=i32, 2=f32

// ---------------------------------------------------------------------------
// 0) sniff mask dtype from its first 64 KB (= uint8 size; safe for all dtypes)
// ---------------------------------------------------------------------------
__global__ void mask_mode_kernel(const unsigned int* __restrict__ w) {
    __shared__ int s_not_int, s_not_flt;
    int tid = threadIdx.x;
    if (tid == 0) { s_not_int = 0; s_not_flt = 0; }
    __syncthreads();
    int not_int = 0, not_flt = 0;
    for (int i = tid; i < (B * T) / 4; i += blockDim.x) {   // 16384 words
        unsigned int x = w[i];
        if (x > 1u) not_int = 1;
        if (x != 0u && x != 0x3F800000u) not_flt = 1;
    }
    if (not_int) atomicOr(&s_not_int, 1);
    if (not_flt) atomicOr(&s_not_flt, 1);
    __syncthreads();
    if (tid == 0)
        g_maskmode = (!s_not_int) ? 1 : ((!s_not_flt) ? 2 : 0);
}

__device__ __forceinline__ bool read_mask(const void* m, int idx, int mode) {
    if (mode == 1) return ((const int*)m)[idx] != 0;
    if (mode == 2) return ((const float*)m)[idx] != 0.f;
    return ((const unsigned char*)m)[idx] != 0;
}

// ---------------------------------------------------------------------------
// 1) q = query @ Wq   [B,A]
// ---------------------------------------------------------------------------
__global__ void qproj_kernel(const float* __restrict__ query,
                             const float* __restrict__ Wq) {
    int b = blockIdx.x;
    int a = threadIdx.x;            // 128 threads
    const float* qb = query + (size_t)b * R;
    float acc = 0.f;
    for (int r = 0; r < R; r++)
        acc += qb[r] * Wq[r * A + a];
    g_q[b * A + a] = acc;
}

// ---------------------------------------------------------------------------
// 2) loc = Wloc^T( BN(relu(conv1d(cat))) )   -> g_loc [B,T,A]
// ---------------------------------------------------------------------------
__global__ void loc_kernel(const float* __restrict__ cat,
                           const float* __restrict__ conv_w,
                           const float* __restrict__ gamma,
                           const float* __restrict__ beta,
                           const float* __restrict__ mean,
                           const float* __restrict__ var,
                           const float* __restrict__ Wloc) {
    int b  = blockIdx.y;
    int t0 = blockIdx.x * 128;
    int j  = threadIdx.x;           // 128 threads

    __shared__ float xs[2][158];            // input slice with halo
    __shared__ float cw[F * 2 * KS];        // conv weights
    __shared__ float feat[F][129];          // conv->relu->bn features

    for (int idx = j; idx < 2 * 158; idx += 128) {
        int ch = idx / 158, p = idx % 158;
        int tt = t0 - PADC + p;
        xs[ch][p] = (tt >= 0 && tt < T) ? cat[(size_t)b * 2 * T + (size_t)ch * T + tt] : 0.f;
    }
    for (int idx = j; idx < F * 2 * KS; idx += 128)
        cw[idx] = conv_w[idx];
    __syncthreads();

    for (int f = 0; f < F; f++) {
        float acc = 0.f;
        #pragma unroll
        for (int ch = 0; ch < 2; ch++)
            #pragma unroll
            for (int k = 0; k < KS; k++)
                acc += xs[ch][j + k] * cw[(f * 2 + ch) * KS + k];
        float val = fmaxf(acc, 0.f);
        val = (val - mean[f]) * (rsqrtf(var[f] + 1e-5f) * gamma[f]) + beta[f];
        feat[f][j] = val;
    }
    __syncthreads();

    float wl[F];
    #pragma unroll
    for (int f = 0; f < F; f++) wl[f] = Wloc[f * A + j];

    float* lp = &g_loc[(size_t)b * T * A + (size_t)t0 * A + j];
    for (int t = 0; t < 128; t++) {
        float acc = 0.f;
        #pragma unroll
        for (int f = 0; f < F; f++) acc += feat[f][t] * wl[f];
        lp[(size_t)t * A] = acc;
    }
}

// ---------------------------------------------------------------------------
// 3) energies: k = key@Wk (tiled smem GEMM, 64x128 per block),
//    e[b,t] = sum_a v[a]*tanh(q + k + loc); masked -> g_e
// ---------------------------------------------------------------------------
__global__ void energy_kernel(const float* __restrict__ key,
                              const float* __restrict__ Wk,
                              const void* __restrict__ mask,
                              const float* __restrict__ v) {
    int b  = blockIdx.y;
    int t0 = blockIdx.x * BT;
    int tid = threadIdx.x;
    int tx = tid & 15;       // 0..15 -> 8 cols each
    int ty = tid >> 4;       // 0..15 -> 4 rows each

    __shared__ float sk[BT][KC + 1];
    __shared__ float sw[KC][A];
    __shared__ float red[BT][17];

    float acc[4][8];
    #pragma unroll
    for (int i = 0; i < 4; i++)
        #pragma unroll
        for (int j = 0; j < 8; j++) acc[i][j] = 0.f;

    const float* keyb = key + (size_t)b * T * E + (size_t)t0 * E;

    for (int e0 = 0; e0 < E; e0 += KC) {
        int kk = tid & 31, rr = tid >> 5;
        #pragma unroll
        for (int i = 0; i < 8; i++)
            sk[rr + i * 8][kk] = keyb[(size_t)(rr + i * 8) * E + e0 + kk];
        int c = tid & 127, k2 = tid >> 7;
        #pragma unroll
        for (int i = 0; i < 16; i++)
            sw[k2 + i * 2][c] = Wk[(size_t)(e0 + k2 + i * 2) * A + c];
        __syncthreads();

        #pragma unroll
        for (int kk2 = 0; kk2 < KC; kk2++) {
            float kv[4], wv[8];
            #pragma unroll
            for (int i = 0; i < 4; i++) kv[i] = sk[ty * 4 + i][kk2];
            #pragma unroll
            for (int j = 0; j < 8; j++) wv[j] = sw[kk2][tx * 8 + j];
            #pragma unroll
            for (int i = 0; i < 4; i++)
                #pragma unroll
                for (int j = 0; j < 8; j++)
                    acc[i][j] += kv[i] * wv[j];
        }
        __syncthreads();
    }

    // epilogue: tanh-energy
    float qv[8], vv[8];
    #pragma unroll
    for (int j = 0; j < 8; j++) {
        int c = tx * 8 + j;
        qv[j] = g_q[b * A + c];
        vv[j] = v[c];
    }
    #pragma unroll
    for (int i = 0; i < 4; i++) {
        int t = t0 + ty * 4 + i;
        const float* lp = &g_loc[(size_t)b * T * A + (size_t)t * A + tx * 8];
        float p = 0.f;
        #pragma unroll
        for (int j = 0; j < 8; j++)
            p += vv[j] * tanhf(qv[j] + acc[i][j] + lp[j]);
        red[ty * 4 + i][tx] = p;
    }
    __syncthreads();
    if (tid < BT) {
        float s = 0.f;
        #pragma unroll
        for (int x = 0; x < 16; x++) s += red[tid][x];
        int t = t0 + tid;
        int mode = g_maskmode;
        g_e[b * T + t] = read_mask(mask, b * T + t, mode) ? -INFINITY : s;
    }
}

// ---------------------------------------------------------------------------
// 4) softmax over T per batch -> weights into d_out[B*E ..]
// ---------------------------------------------------------------------------
__global__ void softmax_kernel(float* __restrict__ out) {
    int b = blockIdx.x;
    int tid = threadIdx.x;          // 256 threads, 4 elems each
    __shared__ float sred[256];

    float vals[4];
    float m = -INFINITY;
    #pragma unroll
    for (int i = 0; i < 4; i++) {
        vals[i] = g_e[b * T + tid + i * 256];
        m = fmaxf(m, vals[i]);
    }
    sred[tid] = m; __syncthreads();
    for (int s = 128; s > 0; s >>= 1) {
        if (tid < s) sred[tid] = fmaxf(sred[tid], sred[tid + s]);
        __syncthreads();
    }
    m = sred[0]; __syncthreads();

    float sum = 0.f;
    #pragma unroll
    for (int i = 0; i < 4; i++) {
        vals[i] = expf(vals[i] - m);
        sum += vals[i];
    }
    sred[tid] = sum; __syncthreads();
    for (int s = 128; s > 0; s >>= 1) {
        if (tid < s) sred[tid] += sred[tid + s];
        __syncthreads();
    }
    float inv = 1.f / sred[0];

    float* w = out + B * E + (size_t)b * T;
    #pragma unroll
    for (int i = 0; i < 4; i++) w[tid + i * 256] = vals[i] * inv;
}

// ---------------------------------------------------------------------------
// 5) context partials: split T into 8 chunks (no atomics -> deterministic)
// ---------------------------------------------------------------------------
__global__ void ctx_part_kernel(const float* __restrict__ key,
                                const float* __restrict__ out) {
    int b = blockIdx.y;
    int chunk = blockIdx.x;         // 0..7, 128 t each
    int e = threadIdx.x;            // 512 threads
    const float* w  = out + B * E + (size_t)b * T + chunk * 128;
    const float* kp = key + (size_t)b * T * E + (size_t)chunk * 128 * E + e;
    float acc = 0.f;
    #pragma unroll 4
    for (int t = 0; t < 128; t++)
        acc += w[t] * kp[(size_t)t * E];
    g_ctxpart[((size_t)b * 8 + chunk) * E + e] = acc;
}

__global__ void ctx_reduce_kernel(float* __restrict__ out) {
    int b = blockIdx.x;
    int e = threadIdx.x;            // 512 threads
    float s = 0.f;
    #pragma unroll
    for (int c = 0; c < 8; c++)
        s += g_ctxpart[((size_t)b * 8 + c) * E + e];
    out[(size_t)b * E + e] = s;
}

// ---------------------------------------------------------------------------
extern "C" void kernel_launch(void* const* d_in, const int* in_sizes, int n_in,
                              void* d_out, int out_size) {
    const float* query  = (const float*)d_in[0];
    const float* key    = (const float*)d_in[1];
    const float* cat    = (const float*)d_in[2];
    const void*  mask   = (const void*)d_in[3];
    const float* Wq     = (const float*)d_in[4];
    const float* Wk     = (const float*)d_in[5];
    const float* conv_w = (const float*)d_in[6];
    const float* gamma  = (const float*)d_in[7];
    const float* beta   = (const float*)d_in[8];
    const float* mean   = (const float*)d_in[9];
    const float* var    = (const float*)d_in[10];
    const float* Wloc   = (const float*)d_in[11];
    const float* v      = (const float*)d_in[12];
    float* out = (float*)d_out;

    mask_mode_kernel<<<1, 256>>>((const unsigned int*)mask);
    qproj_kernel<<<B, A>>>(query, Wq);
    loc_kernel<<<dim3(T / 128, B), 128>>>(cat, conv_w, gamma, beta, mean, var, Wloc);
    energy_kernel<<<dim3(T / BT, B), 256>>>(key, Wk, mask, v);
    softmax_kernel<<<B, 256>>>(out);
    ctx_part_kernel<<<dim3(8, B), E>>>(key, out);
    ctx_reduce_kernel<<<B, E>>>(out);
}

// round 3
// speedup vs baseline: 1.4746x; 1.4746x over previous
#include <cuda_runtime.h>
#include <math.h>

#define B 64
#define T 1024
#define E 512
#define R 1024
#define A 128
#define F 32
#define KS 31
#define PADC 15

#define TM 128          // t-tile of energy GEMM
#define KC 32           // k-chunk

// scratch (allocation-free rule: __device__ globals)
__device__ float  g_q[B * A];                         // 32 KB
__device__ float4 g_feat4[(size_t)B * T * F / 4];     // 8 MB, [B][T][F]
__device__ float  g_e[B * T];                         // 256 KB
__device__ float4 g_ctxpart4[B * 16 * E / 4];         // 2 MB
__device__ int    g_maskmode;                         // 0=u8, 1=i32, 2=f32

// ---------------------------------------------------------------------------
// 0) sniff mask dtype (first 64 KB reinterpreted as u32 — safe for all dtypes)
// ---------------------------------------------------------------------------
__global__ void mask_mode_kernel(const unsigned int* __restrict__ w) {
    __shared__ int s_not_int, s_not_flt;
    int tid = threadIdx.x;
    if (tid == 0) { s_not_int = 0; s_not_flt = 0; }
    __syncthreads();
    int not_int = 0, not_flt = 0;
    for (int i = tid; i < (B * T) / 4; i += blockDim.x) {
        unsigned int x = w[i];
        if (x > 1u) not_int = 1;
        if (x != 0u && x != 0x3F800000u) not_flt = 1;
    }
    if (not_int) atomicOr(&s_not_int, 1);
    if (not_flt) atomicOr(&s_not_flt, 1);
    __syncthreads();
    if (tid == 0)
        g_maskmode = (!s_not_int) ? 1 : ((!s_not_flt) ? 2 : 0);
}

__device__ __forceinline__ bool read_mask(const void* m, int idx, int mode) {
    if (mode == 1) return ((const int*)m)[idx] != 0;
    if (mode == 2) return ((const float*)m)[idx] != 0.f;
    return ((const unsigned char*)m)[idx] != 0;
}

// ---------------------------------------------------------------------------
// 1) q = query @ Wq  [B,A]; split-R over 4 groups + smem reduce
// ---------------------------------------------------------------------------
__global__ void qproj_kernel(const float* __restrict__ query,
                             const float* __restrict__ Wq) {
    int b = blockIdx.x;
    int tid = threadIdx.x;          // 512
    int g = tid >> 7, a = tid & 127;
    __shared__ float sred[4][128];
    const float* qb = query + (size_t)b * R + g * 256;
    const float* wp = Wq + (size_t)(g * 256) * A + a;
    float acc = 0.f;
    #pragma unroll 8
    for (int r = 0; r < 256; r++)
        acc += qb[r] * wp[(size_t)r * A];
    sred[g][a] = acc;
    __syncthreads();
    if (g == 0)
        g_q[b * A + a] = sred[0][a] + sred[1][a] + sred[2][a] + sred[3][a];
}

// ---------------------------------------------------------------------------
// 2) feat = BN(relu(conv1d(cat)))  -> g_feat [B][T][F] (Wloc applied later)
// ---------------------------------------------------------------------------
__global__ void loc_kernel(const float* __restrict__ cat,
                           const float* __restrict__ conv_w,
                           const float* __restrict__ gamma,
                           const float* __restrict__ beta,
                           const float* __restrict__ mean,
                           const float* __restrict__ var) {
    int b  = blockIdx.y;
    int t0 = blockIdx.x * 128;
    int j  = threadIdx.x;           // 128 threads

    __shared__ float xs[2][158];
    __shared__ float cw[F * 2 * KS];
    __shared__ float feat[F][129];

    for (int idx = j; idx < 2 * 158; idx += 128) {
        int ch = idx / 158, p = idx % 158;
        int tt = t0 - PADC + p;
        xs[ch][p] = (tt >= 0 && tt < T) ? cat[(size_t)b * 2 * T + (size_t)ch * T + tt] : 0.f;
    }
    for (int idx = j; idx < F * 2 * KS; idx += 128)
        cw[idx] = conv_w[idx];
    __syncthreads();

    for (int f = 0; f < F; f++) {
        float acc = 0.f;
        #pragma unroll
        for (int ch = 0; ch < 2; ch++)
            #pragma unroll
            for (int k = 0; k < KS; k++)
                acc += xs[ch][j + k] * cw[(f * 2 + ch) * KS + k];
        float val = fmaxf(acc, 0.f);
        val = (val - mean[f]) * (rsqrtf(var[f] + 1e-5f) * gamma[f]) + beta[f];
        feat[f][j] = val;
    }
    __syncthreads();

    // transpose to [T][F] and write coalesced float4
    #pragma unroll
    for (int i = 0; i < 8; i++) {
        int li = j + i * 128;       // 0..1023 float4s
        int t = li >> 3, fg = li & 7;
        float4 v4;
        v4.x = feat[fg * 4 + 0][t];
        v4.y = feat[fg * 4 + 1][t];
        v4.z = feat[fg * 4 + 2][t];
        v4.w = feat[fg * 4 + 3][t];
        g_feat4[((size_t)b * T + t0 + t) * (F / 4) + fg] = v4;
    }
}

// ---------------------------------------------------------------------------
// 3) energies: k = key@Wk (128x128 tile, 8x8 microtile, float4 LDS),
//    + inline loc = feat@Wloc, then e[b,t] = sum_a v[a]*tanh(q+k+loc)
// ---------------------------------------------------------------------------
__global__ void __launch_bounds__(256, 2)
energy_kernel(const float* __restrict__ key,
              const float* __restrict__ Wk,
              const float* __restrict__ Wloc,
              const void* __restrict__ mask,
              const float* __restrict__ v) {
    int b  = blockIdx.y;
    int t0 = blockIdx.x * TM;
    int tid = threadIdx.x;
    int tx = tid & 15;              // 16 cols-of-8
    int ty = tid >> 4;              // 16 rows-of-8

    __shared__ float pool[8704];    // 34.8 KB, reused across stages
    float* skT = pool;              // [KC][TM+4] = [32][132]
    float* sw  = pool + 4224;       // [KC][A+4]  = [32][132]

    float acc[8][8];
    #pragma unroll
    for (int i = 0; i < 8; i++)
        #pragma unroll
        for (int j = 0; j < 8; j++) acc[i][j] = 0.f;

    const float* keyb = key + (size_t)b * T * E + (size_t)t0 * E;

    for (int e0 = 0; e0 < E; e0 += KC) {
        // key tile 128x32, transpose into skT
        #pragma unroll
        for (int i = 0; i < 4; i++) {
            int li = tid + i * 256;
            int row = li >> 3, cg = li & 7;
            float4 k4 = *(const float4*)(keyb + (size_t)row * E + e0 + cg * 4);
            skT[(cg * 4 + 0) * 132 + row] = k4.x;
            skT[(cg * 4 + 1) * 132 + row] = k4.y;
            skT[(cg * 4 + 2) * 132 + row] = k4.z;
            skT[(cg * 4 + 3) * 132 + row] = k4.w;
        }
        // Wk tile 32x128 direct
        #pragma unroll
        for (int i = 0; i < 4; i++) {
            int li = tid + i * 256;
            int row = li >> 5, cg = li & 31;
            *(float4*)(sw + row * 132 + cg * 4) =
                *(const float4*)(Wk + (size_t)(e0 + row) * A + cg * 4);
        }
        __syncthreads();

        #pragma unroll
        for (int kk = 0; kk < KC; kk++) {
            float4 a0 = *(float4*)(skT + kk * 132 + ty * 8);
            float4 a1 = *(float4*)(skT + kk * 132 + ty * 8 + 4);
            float4 b0 = *(float4*)(sw  + kk * 132 + tx * 8);
            float4 b1 = *(float4*)(sw  + kk * 132 + tx * 8 + 4);
            float av[8] = {a0.x, a0.y, a0.z, a0.w, a1.x, a1.y, a1.z, a1.w};
            float bv[8] = {b0.x, b0.y, b0.z, b0.w, b1.x, b1.y, b1.z, b1.w};
            #pragma unroll
            for (int i = 0; i < 8; i++)
                #pragma unroll
                for (int j = 0; j < 8; j++)
                    acc[i][j] += av[i] * bv[j];
        }
        __syncthreads();
    }

    // ---- stage 2: inline loc = feat @ Wloc, accumulate into acc ----
    float* featS = pool;            // [TM][F+4] = [128][36]
    float* WlocS = pool + 4608;     // [F][A]    = [32][128]
    #pragma unroll
    for (int i = 0; i < 4; i++) {
        int li = tid + i * 256;     // 1024 float4s of feat tile
        int t = li >> 3, fg = li & 7;
        float4 f4 = g_feat4[((size_t)b * T + t0 + t) * (F / 4) + fg];
        *(float4*)(featS + t * 36 + fg * 4) = f4;
    }
    #pragma unroll
    for (int i = 0; i < 4; i++) {
        int li = tid + i * 256;     // 1024 float4s of Wloc
        int f = li >> 5, cg = li & 31;
        *(float4*)(WlocS + f * 128 + cg * 4) = *(const float4*)(Wloc + f * 128 + cg * 4);
    }
    __syncthreads();

    #pragma unroll
    for (int f = 0; f < F; f++) {
        float4 w0 = *(float4*)(WlocS + f * 128 + tx * 8);
        float4 w1 = *(float4*)(WlocS + f * 128 + tx * 8 + 4);
        #pragma unroll
        for (int i = 0; i < 8; i++) {
            float ft = featS[(ty * 8 + i) * 36 + f];
            acc[i][0] += ft * w0.x; acc[i][1] += ft * w0.y;
            acc[i][2] += ft * w0.z; acc[i][3] += ft * w0.w;
            acc[i][4] += ft * w1.x; acc[i][5] += ft * w1.y;
            acc[i][6] += ft * w1.z; acc[i][7] += ft * w1.w;
        }
    }

    // ---- energies ----
    float4 q0 = *(const float4*)(g_q + b * A + tx * 8);
    float4 q1 = *(const float4*)(g_q + b * A + tx * 8 + 4);
    float4 v0 = *(const float4*)(v + tx * 8);
    float4 v1 = *(const float4*)(v + tx * 8 + 4);
    float qv[8] = {q0.x, q0.y, q0.z, q0.w, q1.x, q1.y, q1.z, q1.w};
    float vv[8] = {v0.x, v0.y, v0.z, v0.w, v1.x, v1.y, v1.z, v1.w};

    float p[8];
    #pragma unroll
    for (int i = 0; i < 8; i++) {
        float s = 0.f;
        #pragma unroll
        for (int j = 0; j < 8; j++)
            s += vv[j] * tanhf(qv[j] + acc[i][j]);
        p[i] = s;
    }
    __syncthreads();                 // done reading featS/WlocS

    float* red = pool;               // [128][17]
    #pragma unroll
    for (int i = 0; i < 8; i++)
        red[(ty * 8 + i) * 17 + tx] = p[i];
    __syncthreads();

    if (tid < TM) {
        float s = 0.f;
        #pragma unroll
        for (int x = 0; x < 16; x++) s += red[tid * 17 + x];
        int t = t0 + tid;
        int mode = g_maskmode;
        g_e[b * T + t] = read_mask(mask, b * T + t, mode) ? -INFINITY : s;
    }
}

// ---------------------------------------------------------------------------
// 4) softmax over T per batch -> weights into d_out[B*E ..]
// ---------------------------------------------------------------------------
__global__ void softmax_kernel(float* __restrict__ out) {
    int b = blockIdx.x;
    int tid = threadIdx.x;          // 256 threads, 4 elems each
    __shared__ float sred[256];

    float vals[4];
    float m = -INFINITY;
    #pragma unroll
    for (int i = 0; i < 4; i++) {
        vals[i] = g_e[b * T + tid + i * 256];
        m = fmaxf(m, vals[i]);
    }
    sred[tid] = m; __syncthreads();
    for (int s = 128; s > 0; s >>= 1) {
        if (tid < s) sred[tid] = fmaxf(sred[tid], sred[tid + s]);
        __syncthreads();
    }
    m = sred[0]; __syncthreads();

    float sum = 0.f;
    #pragma unroll
    for (int i = 0; i < 4; i++) {
        vals[i] = expf(vals[i] - m);
        sum += vals[i];
    }
    sred[tid] = sum; __syncthreads();
    for (int s = 128; s > 0; s >>= 1) {
        if (tid < s) sred[tid] += sred[tid + s];
        __syncthreads();
    }
    float inv = 1.f / sred[0];

    float* w = out + B * E + (size_t)b * T;
    #pragma unroll
    for (int i = 0; i < 4; i++) w[tid + i * 256] = vals[i] * inv;
}

// ---------------------------------------------------------------------------
// 5) context: 16 T-chunks x float4 columns, then reduce (deterministic)
// ---------------------------------------------------------------------------
__global__ void ctx_part_kernel(const float* __restrict__ key,
                                const float* __restrict__ out) {
    int b = blockIdx.y;
    int c = blockIdx.x;             // 0..15, 64 t each
    int e4 = threadIdx.x;           // 128 float4 columns
    const float* w = out + B * E + (size_t)b * T + c * 64;
    const float4* kp = (const float4*)(key + (size_t)b * T * E) + (size_t)c * 64 * (E / 4) + e4;
    float4 acc = make_float4(0.f, 0.f, 0.f, 0.f);
    #pragma unroll 4
    for (int t = 0; t < 64; t++) {
        float4 k4 = kp[(size_t)t * (E / 4)];
        float wt = w[t];
        acc.x += wt * k4.x; acc.y += wt * k4.y;
        acc.z += wt * k4.z; acc.w += wt * k4.w;
    }
    g_ctxpart4[(b * 16 + c) * (E / 4) + e4] = acc;
}

__global__ void ctx_reduce_kernel(float* __restrict__ out) {
    int b = blockIdx.x;
    int e4 = threadIdx.x;           // 128
    float4 s = make_float4(0.f, 0.f, 0.f, 0.f);
    #pragma unroll
    for (int c = 0; c < 16; c++) {
        float4 p = g_ctxpart4[(b * 16 + c) * (E / 4) + e4];
        s.x += p.x; s.y += p.y; s.z += p.z; s.w += p.w;
    }
    float* o = out + (size_t)b * E + e4 * 4;
    o[0] = s.x; o[1] = s.y; o[2] = s.z; o[3] = s.w;
}

// ---------------------------------------------------------------------------
extern "C" void kernel_launch(void* const* d_in, const int* in_sizes, int n_in,
                              void* d_out, int out_size) {
    const float* query  = (const float*)d_in[0];
    const float* key    = (const float*)d_in[1];
    const float* cat    = (const float*)d_in[2];
    const void*  mask   = (const void*)d_in[3];
    const float* Wq     = (const float*)d_in[4];
    const float* Wk     = (const float*)d_in[5];
    const float* conv_w = (const float*)d_in[6];
    const float* gamma  = (const float*)d_in[7];
    const float* beta   = (const float*)d_in[8];
    const float* mean   = (const float*)d_in[9];
    const float* var    = (const float*)d_in[10];
    const float* Wloc   = (const float*)d_in[11];
    const float* v      = (const float*)d_in[12];
    float* out = (float*)d_out;

    mask_mode_kernel<<<1, 256>>>((const unsigned int*)mask);
    qproj_kernel<<<B, 512>>>(query, Wq);
    loc_kernel<<<dim3(T / 128, B), 128>>>(cat, conv_w, gamma, beta, mean, var);
    energy_kernel<<<dim3(T / TM, B), 256>>>(key, Wk, Wloc, mask, v);
    softmax_kernel<<<B, 256>>>(out);
    ctx_part_kernel<<<dim3(16, B), 128>>>(key, out);
    ctx_reduce_kernel<<<B, 128>>>(out);
}

// round 4
// speedup vs baseline: 2.8674x; 1.9445x over previous
#include <cuda_runtime.h>
#include <math.h>
#include <stdint.h>

#define B 64
#define T 1024
#define E 512
#define R 1024
#define A 128
#define F 32
#define KS 31
#define PADC 15

#define TM 128          // t-tile of energy GEMM
#define KC 32           // k-chunk
#define SA 36           // skA stride (conflict-free A frags)
#define SB 136          // swB stride (conflict-free B frags)

// scratch (allocation-free rule: __device__ globals)
__device__ float  g_q[B * A];                         // 32 KB
__device__ float4 g_feat4[(size_t)B * T * F / 4];     // 8 MB, [B][T][F]
__device__ float  g_e[B * T];                         // 256 KB
__device__ float4 g_ctxpart4[B * 16 * E / 4];         // 2 MB
__device__ int    g_maskmode;                         // 0=u8, 1=i32, 2=f32

__device__ __forceinline__ float to_tf32(float x) {
    uint32_t u;
    asm("cvt.rna.tf32.f32 %0, %1;" : "=r"(u) : "f"(x));
    return __uint_as_float(u);
}

// ---------------------------------------------------------------------------
// 0) sniff mask dtype (first 64 KB reinterpreted as u32 — safe for all dtypes)
// ---------------------------------------------------------------------------
__global__ void mask_mode_kernel(const unsigned int* __restrict__ w) {
    __shared__ int s_not_int, s_not_flt;
    int tid = threadIdx.x;
    if (tid == 0) { s_not_int = 0; s_not_flt = 0; }
    __syncthreads();
    int not_int = 0, not_flt = 0;
    for (int i = tid; i < (B * T) / 4; i += blockDim.x) {
        unsigned int x = w[i];
        if (x > 1u) not_int = 1;
        if (x != 0u && x != 0x3F800000u) not_flt = 1;
    }
    if (not_int) atomicOr(&s_not_int, 1);
    if (not_flt) atomicOr(&s_not_flt, 1);
    __syncthreads();
    if (tid == 0)
        g_maskmode = (!s_not_int) ? 1 : ((!s_not_flt) ? 2 : 0);
}

__device__ __forceinline__ bool read_mask(const void* m, int idx, int mode) {
    if (mode == 1) return ((const int*)m)[idx] != 0;
    if (mode == 2) return ((const float*)m)[idx] != 0.f;
    return ((const unsigned char*)m)[idx] != 0;
}

// ---------------------------------------------------------------------------
// 1) q = query @ Wq  [B,A]; split-R over 4 groups + smem reduce
// ---------------------------------------------------------------------------
__global__ void qproj_kernel(const float* __restrict__ query,
                             const float* __restrict__ Wq) {
    int b = blockIdx.x;
    int tid = threadIdx.x;          // 512
    int g = tid >> 7, a = tid & 127;
    __shared__ float sred[4][128];
    const float* qb = query + (size_t)b * R + g * 256;
    const float* wp = Wq + (size_t)(g * 256) * A + a;
    float acc = 0.f;
    #pragma unroll 8
    for (int r = 0; r < 256; r++)
        acc += qb[r] * wp[(size_t)r * A];
    sred[g][a] = acc;
    __syncthreads();
    if (g == 0)
        g_q[b * A + a] = sred[0][a] + sred[1][a] + sred[2][a] + sred[3][a];
}

// ---------------------------------------------------------------------------
// 2) feat = BN(relu(conv1d(cat)))  -> g_feat [B][T][F]
// ---------------------------------------------------------------------------
__global__ void loc_kernel(const float* __restrict__ cat,
                           const float* __restrict__ conv_w,
                           const float* __restrict__ gamma,
                           const float* __restrict__ beta,
                           const float* __restrict__ mean,
                           const float* __restrict__ var) {
    int b  = blockIdx.y;
    int t0 = blockIdx.x * 128;
    int j  = threadIdx.x;           // 128 threads

    __shared__ float xs[2][158];
    __shared__ float cw[F * 2 * KS];
    __shared__ float feat[F][129];

    for (int idx = j; idx < 2 * 158; idx += 128) {
        int ch = idx / 158, p = idx % 158;
        int tt = t0 - PADC + p;
        xs[ch][p] = (tt >= 0 && tt < T) ? cat[(size_t)b * 2 * T + (size_t)ch * T + tt] : 0.f;
    }
    for (int idx = j; idx < F * 2 * KS; idx += 128)
        cw[idx] = conv_w[idx];
    __syncthreads();

    for (int f = 0; f < F; f++) {
        float acc = 0.f;
        #pragma unroll
        for (int ch = 0; ch < 2; ch++)
            #pragma unroll
            for (int k = 0; k < KS; k++)
                acc += xs[ch][j + k] * cw[(f * 2 + ch) * KS + k];
        float val = fmaxf(acc, 0.f);
        val = (val - mean[f]) * (rsqrtf(var[f] + 1e-5f) * gamma[f]) + beta[f];
        feat[f][j] = val;
    }
    __syncthreads();

    #pragma unroll
    for (int i = 0; i < 8; i++) {
        int li = j + i * 128;       // 0..1023 float4s
        int t = li >> 3, fg = li & 7;
        float4 v4;
        v4.x = feat[fg * 4 + 0][t];
        v4.y = feat[fg * 4 + 1][t];
        v4.z = feat[fg * 4 + 2][t];
        v4.w = feat[fg * 4 + 3][t];
        g_feat4[((size_t)b * T + t0 + t) * (F / 4) + fg] = v4;
    }
}

// ---------------------------------------------------------------------------
// 3) energy: tf32 tensor-core GEMM 128x128x(512+32)
//    S = key@Wk + feat@Wloc, then e[t] = sum_a v[a]*tanh(q[a]+S[t,a])
// ---------------------------------------------------------------------------
__device__ __forceinline__ void mma_tf32(float& c0, float& c1, float& c2, float& c3,
                                         uint32_t a0, uint32_t a1, uint32_t a2, uint32_t a3,
                                         uint32_t b0, uint32_t b1) {
    asm volatile(
        "mma.sync.aligned.m16n8k8.row.col.f32.tf32.tf32.f32 "
        "{%0,%1,%2,%3}, {%4,%5,%6,%7}, {%8,%9}, {%0,%1,%2,%3};"
        : "+f"(c0), "+f"(c1), "+f"(c2), "+f"(c3)
        : "r"(a0), "r"(a1), "r"(a2), "r"(a3), "r"(b0), "r"(b1));
}

__global__ void __launch_bounds__(256, 2)
energy_kernel(const float* __restrict__ key,
              const float* __restrict__ Wk,
              const float* __restrict__ Wloc,
              const void* __restrict__ mask,
              const float* __restrict__ v) {
    int b  = blockIdx.y;
    int t0 = blockIdx.x * TM;
    int tid = threadIdx.x;
    int lane = tid & 31;
    int wid  = tid >> 5;
    int warp_m = wid >> 2;          // 0..1 (64 rows each)
    int warp_n = wid & 3;           // 0..3 (32 cols each)

    __shared__ float skA[TM * SA];  // [128][36] tf32 key/feat tile
    __shared__ float swB[KC * SB];  // [32][136] tf32 Wk/Wloc tile

    float acc[4][4][4];             // [mfrag][nfrag][reg]
    #pragma unroll
    for (int i = 0; i < 4; i++)
        #pragma unroll
        for (int j = 0; j < 4; j++)
            #pragma unroll
            for (int r = 0; r < 4; r++) acc[i][j][r] = 0.f;

    const float* keyb = key + (size_t)b * T * E + (size_t)t0 * E;

    for (int chunk = 0; chunk < 17; chunk++) {
        // ---- load A tile (key 128x32 or feat 128x32) ----
        if (chunk < 16) {
            int e0 = chunk * KC;
            #pragma unroll
            for (int i = 0; i < 4; i++) {
                int li = tid + i * 256;
                int row = li >> 3, cg = li & 7;
                float4 k4 = *(const float4*)(keyb + (size_t)row * E + e0 + cg * 4);
                float4 t4 = make_float4(to_tf32(k4.x), to_tf32(k4.y),
                                        to_tf32(k4.z), to_tf32(k4.w));
                *(float4*)(skA + row * SA + cg * 4) = t4;
            }
            #pragma unroll
            for (int i = 0; i < 4; i++) {
                int li = tid + i * 256;
                int row = li >> 5, cg = li & 31;
                float4 w4 = *(const float4*)(Wk + (size_t)(e0 + row) * A + cg * 4);
                float4 t4 = make_float4(to_tf32(w4.x), to_tf32(w4.y),
                                        to_tf32(w4.z), to_tf32(w4.w));
                *(float4*)(swB + row * SB + cg * 4) = t4;
            }
        } else {
            #pragma unroll
            for (int i = 0; i < 4; i++) {
                int li = tid + i * 256;
                int row = li >> 3, fg = li & 7;
                float4 f4 = g_feat4[((size_t)b * T + t0 + row) * (F / 4) + fg];
                float4 t4 = make_float4(to_tf32(f4.x), to_tf32(f4.y),
                                        to_tf32(f4.z), to_tf32(f4.w));
                *(float4*)(skA + row * SA + fg * 4) = t4;
            }
            #pragma unroll
            for (int i = 0; i < 4; i++) {
                int li = tid + i * 256;
                int row = li >> 5, cg = li & 31;
                float4 w4 = *(const float4*)(Wloc + row * A + cg * 4);
                float4 t4 = make_float4(to_tf32(w4.x), to_tf32(w4.y),
                                        to_tf32(w4.z), to_tf32(w4.w));
                *(float4*)(swB + row * SB + cg * 4) = t4;
            }
        }
        __syncthreads();

        // ---- 4 k-steps of m16n8k8 ----
        #pragma unroll
        for (int ks = 0; ks < 4; ks++) {
            int k0 = ks * 8;
            uint32_t af[4][4];
            #pragma unroll
            for (int mf = 0; mf < 4; mf++) {
                int rbase = warp_m * 64 + mf * 16 + (lane >> 2);
                int kcol = k0 + (lane & 3);
                af[mf][0] = __float_as_uint(skA[rbase * SA + kcol]);
                af[mf][1] = __float_as_uint(skA[(rbase + 8) * SA + kcol]);
                af[mf][2] = __float_as_uint(skA[rbase * SA + kcol + 4]);
                af[mf][3] = __float_as_uint(skA[(rbase + 8) * SA + kcol + 4]);
            }
            uint32_t bf[4][2];
            #pragma unroll
            for (int nf = 0; nf < 4; nf++) {
                int col = warp_n * 32 + nf * 8 + (lane >> 2);
                int krow = k0 + (lane & 3);
                bf[nf][0] = __float_as_uint(swB[krow * SB + col]);
                bf[nf][1] = __float_as_uint(swB[(krow + 4) * SB + col]);
            }
            #pragma unroll
            for (int mf = 0; mf < 4; mf++)
                #pragma unroll
                for (int nf = 0; nf < 4; nf++)
                    mma_tf32(acc[mf][nf][0], acc[mf][nf][1],
                             acc[mf][nf][2], acc[mf][nf][3],
                             af[mf][0], af[mf][1], af[mf][2], af[mf][3],
                             bf[nf][0], bf[nf][1]);
        }
        __syncthreads();
    }

    // ---- epilogue: e[t] = sum_a v[a] * tanh(q[a] + S[t,a]) ----
    float part[4][2];
    #pragma unroll
    for (int mf = 0; mf < 4; mf++) { part[mf][0] = 0.f; part[mf][1] = 0.f; }

    #pragma unroll
    for (int nf = 0; nf < 4; nf++) {
        int c0 = warp_n * 32 + nf * 8 + 2 * (lane & 3);
        float qv0 = g_q[b * A + c0],     qv1 = g_q[b * A + c0 + 1];
        float vv0 = v[c0],               vv1 = v[c0 + 1];
        #pragma unroll
        for (int mf = 0; mf < 4; mf++) {
            part[mf][0] += vv0 * tanhf(qv0 + acc[mf][nf][0])
                         + vv1 * tanhf(qv1 + acc[mf][nf][1]);
            part[mf][1] += vv0 * tanhf(qv0 + acc[mf][nf][2])
                         + vv1 * tanhf(qv1 + acc[mf][nf][3]);
        }
    }

    float* red = skA;                // reuse: [128][5]
    #pragma unroll
    for (int mf = 0; mf < 4; mf++) {
        #pragma unroll
        for (int r = 0; r < 2; r++) {
            float p = part[mf][r];
            p += __shfl_xor_sync(0xFFFFFFFFu, p, 1);
            p += __shfl_xor_sync(0xFFFFFFFFu, p, 2);
            if ((lane & 3) == 0) {
                int row = warp_m * 64 + mf * 16 + (lane >> 2) + r * 8;
                red[row * 5 + warp_n] = p;
            }
        }
    }
    __syncthreads();

    if (tid < TM) {
        float s = red[tid * 5 + 0] + red[tid * 5 + 1]
                + red[tid * 5 + 2] + red[tid * 5 + 3];
        int t = t0 + tid;
        int mode = g_maskmode;
        g_e[b * T + t] = read_mask(mask, b * T + t, mode) ? -INFINITY : s;
    }
}

// ---------------------------------------------------------------------------
// 4) softmax over T per batch -> weights into d_out[B*E ..]
// ---------------------------------------------------------------------------
__global__ void softmax_kernel(float* __restrict__ out) {
    int b = blockIdx.x;
    int tid = threadIdx.x;          // 256 threads, 4 elems each
    __shared__ float sred[256];

    float vals[4];
    float m = -INFINITY;
    #pragma unroll
    for (int i = 0; i < 4; i++) {
        vals[i] = g_e[b * T + tid + i * 256];
        m = fmaxf(m, vals[i]);
    }
    sred[tid] = m; __syncthreads();
    for (int s = 128; s > 0; s >>= 1) {
        if (tid < s) sred[tid] = fmaxf(sred[tid], sred[tid + s]);
        __syncthreads();
    }
    m = sred[0]; __syncthreads();

    float sum = 0.f;
    #pragma unroll
    for (int i = 0; i < 4; i++) {
        vals[i] = expf(vals[i] - m);
        sum += vals[i];
    }
    sred[tid] = sum; __syncthreads();
    for (int s = 128; s > 0; s >>= 1) {
        if (tid < s) sred[tid] += sred[tid + s];
        __syncthreads();
    }
    float inv = 1.f / sred[0];

    float* w = out + B * E + (size_t)b * T;
    #pragma unroll
    for (int i = 0; i < 4; i++) w[tid + i * 256] = vals[i] * inv;
}

// ---------------------------------------------------------------------------
// 5) context: 16 T-chunks x float4 columns, then reduce (deterministic)
// ---------------------------------------------------------------------------
__global__ void ctx_part_kernel(const float* __restrict__ key,
                                const float* __restrict__ out) {
    int b = blockIdx.y;
    int c = blockIdx.x;             // 0..15, 64 t each
    int e4 = threadIdx.x;           // 128 float4 columns
    const float* w = out + B * E + (size_t)b * T + c * 64;
    const float4* kp = (const float4*)(key + (size_t)b * T * E) + (size_t)c * 64 * (E / 4) + e4;
    float4 acc = make_float4(0.f, 0.f, 0.f, 0.f);
    #pragma unroll 4
    for (int t = 0; t < 64; t++) {
        float4 k4 = kp[(size_t)t * (E / 4)];
        float wt = w[t];
        acc.x += wt * k4.x; acc.y += wt * k4.y;
        acc.z += wt * k4.z; acc.w += wt * k4.w;
    }
    g_ctxpart4[(b * 16 + c) * (E / 4) + e4] = acc;
}

__global__ void ctx_reduce_kernel(float* __restrict__ out) {
    int b = blockIdx.x;
    int e4 = threadIdx.x;           // 128
    float4 s = make_float4(0.f, 0.f, 0.f, 0.f);
    #pragma unroll
    for (int c = 0; c < 16; c++) {
        float4 p = g_ctxpart4[(b * 16 + c) * (E / 4) + e4];
        s.x += p.x; s.y += p.y; s.z += p.z; s.w += p.w;
    }
    float* o = out + (size_t)b * E + e4 * 4;
    o[0] = s.x; o[1] = s.y; o[2] = s.z; o[3] = s.w;
}

// ---------------------------------------------------------------------------
extern "C" void kernel_launch(void* const* d_in, const int* in_sizes, int n_in,
                              void* d_out, int out_size) {
    const float* query  = (const float*)d_in[0];
    const float* key    = (const float*)d_in[1];
    const float* cat    = (const float*)d_in[2];
    const void*  mask   = (const void*)d_in[3];
    const float* Wq     = (const float*)d_in[4];
    const float* Wk     = (const float*)d_in[5];
    const float* conv_w = (const float*)d_in[6];
    const float* gamma  = (const float*)d_in[7];
    const float* beta   = (const float*)d_in[8];
    const float* mean   = (const float*)d_in[9];
    const float* var    = (const float*)d_in[10];
    const float* Wloc   = (const float*)d_in[11];
    const float* v      = (const float*)d_in[12];
    float* out = (float*)d_out;

    mask_mode_kernel<<<1, 256>>>((const unsigned int*)mask);
    qproj_kernel<<<B, 512>>>(query, Wq);
    loc_kernel<<<dim3(T / 128, B), 128>>>(cat, conv_w, gamma, beta, mean, var);
    energy_kernel<<<dim3(T / TM, B), 256>>>(key, Wk, Wloc, mask, v);
    softmax_kernel<<<B, 256>>>(out);
    ctx_part_kernel<<<dim3(16, B), 128>>>(key, out);
    ctx_reduce_kernel<<<B, 128>>>(out);
}